// round 15
// baseline (speedup 1.0000x reference)
#include <cuda_runtime.h>
#include <math.h>

#define NB 1024
#define NC 150
#define NCP 152     // padded channel stride (float4-aligned); pad stays 0
#define NH 14
#define NS 196      // 14*14
#define ND 32
#define NLOC (NB * NS)
#define TOTP (NS * NCP)   // padded per-sample extent = 29792
#define KGLB 2352   // ceil(0.08 * 150*196)
#define NHEAD 4
#define HD 8
#define SMEM_A_BYTES (TOTP * 4)   // 119168 B: whole sample in smem

typedef unsigned long long u64;

__device__ __forceinline__ u64 pack2(float lo, float hi) {
    u64 r; asm("mov.b64 %0, {%1, %2};" : "=l"(r) : "f"(lo), "f"(hi)); return r;
}
__device__ __forceinline__ void unpack2(u64 v, float& lo, float& hi) {
    asm("mov.b64 {%0, %1}, %2;" : "=f"(lo), "=f"(hi) : "l"(v));
}
__device__ __forceinline__ void ffma2(u64& d, u64 a, u64 b) {
    asm("fma.rn.f32x2 %0, %1, %2, %0;" : "+l"(d) : "l"(a), "l"(b));
}
__device__ __forceinline__ u64 fmul2(u64 a, u64 b) {
    u64 r; asm("mul.rn.f32x2 %0, %1, %2;" : "=l"(r) : "l"(a), "l"(b)); return r;
}

__device__ float g_A[(size_t)NB * TOTP];           // [b][s][c], c-pad zeroed
__device__ unsigned g_hist[(size_t)NB * 256];      // level-0 hist (from conv)
__device__ unsigned g_maxu[NB];                    // per-sample max (uint view)
__device__ float g_tv[(size_t)10 * NLOC];          // SoA filtered top-10 vals
__device__ unsigned char g_tcb[(size_t)10 * NLOC]; // SoA top-10 channel idx
__device__ u64 g_wT2[81 * NC];                     // [k][c] = (w,w) splat
__device__ float g_pe[NS * ND];                    // 2D sinusoidal PE table
__device__ float g_thr[NB];
__device__ float g_gmax[NB];
__device__ float g_q[(size_t)NB * NHEAD * NS * HD];
__device__ float g_k[(size_t)NB * NHEAD * NS * HD];
__device__ float g_v[(size_t)NB * NHEAD * NS * HD];
__device__ float g_ctx[(size_t)NB * NS * ND];

// ---------------------------------------------------------------------------
// Kernel 0a: pre-splat conv weights + zero hist/max (graph-replay safe).
// ---------------------------------------------------------------------------
__global__ void prep_w_kernel(const float* __restrict__ w) {
    int i = blockIdx.x * blockDim.x + threadIdx.x;
    if (i < 81 * NC) {
        int k = i / NC, c = i - k * NC;
        float v = w[c * 81 + k];
        g_wT2[i] = pack2(v, v);
    }
    if (i < NB * 256) g_hist[i] = 0u;
    if (i < NB) g_maxu[i] = 0u;
}

// ---------------------------------------------------------------------------
// Kernel 0b: 2D sinusoidal PE table (batch-independent).
// ---------------------------------------------------------------------------
__global__ void pe_kernel() {
    int s = blockIdx.x;
    int d = threadIdx.x;
    int y = s / NH, xx = s - y * NH;
    const float c0 = -(logf(10000.0f) / 16.0f);
    float pe;
    if (d < 16) {
        int j = d >> 1;
        float div = expf(c0 * (float)(2 * j));
        float ang = (float)y * div;
        pe = (d & 1) ? cosf(ang) : sinf(ang);
    } else {
        int dd = d - 16;
        int j = dd >> 1;
        float div = expf(c0 * (float)(2 * j));
        float ang = (float)xx * div;
        pe = (dd & 1) ? cosf(ang) : sinf(ang);
    }
    g_pe[s * ND + d] = pe;
}

// ---------------------------------------------------------------------------
// Kernel 1: conv 9x9 stride2 pad4 + ReLU, f32x2 over ow-pairs.
// FUSED: level-0 radix hist + per-sample max (proven R9 version, unchanged).
// ---------------------------------------------------------------------------
__global__ void __launch_bounds__(160) conv_kernel(const float* __restrict__ x) {
    __shared__ float row[9][36];
    __shared__ u64 row2[9][33];
    __shared__ unsigned s_hist[256];
    __shared__ unsigned s_maxu;
    int b = blockIdx.x / NH;
    int oh = blockIdx.x % NH;
    int tid = threadIdx.x;

    for (int i = tid; i < 9 * 36; i += 160)
        (&row[0][0])[i] = 0.0f;
    for (int i = tid; i < 256; i += 160) s_hist[i] = 0u;
    if (tid == 0) s_maxu = 0u;
    __syncthreads();
    for (int i = tid; i < 9 * 28; i += 160) {
        int kh = i / 28, iw = i % 28;
        int ih = oh * 2 - 4 + kh;
        if (ih >= 0 && ih < 28)
            row[kh][iw + 4] = x[((size_t)b * 28 + ih) * 28 + iw];
    }
    __syncthreads();
    for (int i = tid; i < 9 * 33; i += 160) {
        int kh = i / 33, j = i - kh * 33;
        row2[kh][j] = pack2(row[kh][j], row[kh][j + 2]);
    }
    __syncthreads();

    int c = tid;
    if (c < NC) {
        u64 acc[7];
#pragma unroll
        for (int p = 0; p < 7; ++p) acc[p] = 0;
        for (int kh = 0; kh < 9; ++kh) {
            u64 rr2[33];
#pragma unroll
            for (int j = 0; j < 33; ++j) rr2[j] = row2[kh][j];
            const u64* wp = &g_wT2[(kh * 9) * NC + c];
#pragma unroll
            for (int kw = 0; kw < 9; ++kw) {
                u64 w2 = wp[kw * NC];
#pragma unroll
                for (int p = 0; p < 7; ++p)
                    ffma2(acc[p], w2, rr2[4 * p + kw]);
            }
        }
        float* out = &g_A[((size_t)b * NS + oh * NH) * NCP + c];
        unsigned mymax = 0u;
#pragma unroll
        for (int p = 0; p < 7; ++p) {
            float lo, hi; unpack2(acc[p], lo, hi);
            lo = fmaxf(lo, 0.0f);
            hi = fmaxf(hi, 0.0f);
            out[(size_t)(2 * p) * NCP] = lo;
            out[(size_t)(2 * p + 1) * NCP] = hi;
            unsigned ul = __float_as_uint(lo);
            unsigned uh = __float_as_uint(hi);
            mymax = max(mymax, max(ul, uh));
            if (ul) atomicAdd(&s_hist[ul >> 24], 1u);
            if (uh) atomicAdd(&s_hist[uh >> 24], 1u);
        }
        atomicMax(&s_maxu, mymax);
    }
    __syncthreads();
    for (int i = tid; i < 256; i += 160) {
        unsigned cc = s_hist[i];
        if (cc) atomicAdd(&g_hist[(size_t)b * 256 + i], cc);
    }
    if (tid == 0) atomicMax(&g_maxu[b], s_maxu);
}

// ---------------------------------------------------------------------------
// Kernel 2 (MONOLITH): one block per sample, whole sample in SMEM.
//  - load 116 KB sample (coalesced, ONE DRAM read of g_A total)
//  - radix levels 1-3 re-scan SMEM (no candidate lists, no global atomics)
//    with parallel suffix-scan bin selection
//  - per-location filtered top-10 from SMEM (exact R9 logic) -> SoA out
// ---------------------------------------------------------------------------
__global__ void __launch_bounds__(512) sample_kernel() {
    extern __shared__ float sA[];
    __shared__ unsigned h[256];
    __shared__ unsigned S[256];
    __shared__ unsigned s_prefix;
    __shared__ int s_k;
    int b = blockIdx.x;
    int tid = threadIdx.x;

    // ---- load sample into smem ----
    const float4* g4 = (const float4*)(g_A + (size_t)b * TOTP);
    float4* s4 = (float4*)sA;
    for (int i = tid; i < TOTP / 4; i += 512) s4[i] = g4[i];

    // ---- level 0: from conv-built hist ----
    if (tid < 256) h[tid] = g_hist[(size_t)b * 256 + tid];
    __syncthreads();

#pragma unroll 1
    for (int level = 0; level < 4; ++level) {
        // build hist for levels 1..3 from smem (level 0 uses conv's hist)
        if (level > 0) {
            unsigned prefix;
            int kcur;
            prefix = s_prefix; kcur = s_k; (void)kcur;
            if (tid < 256) S[tid] = 0;   // reuse S as scratch? no: clear h
            __syncthreads();
            if (tid < 256) h[tid] = 0;
            __syncthreads();
            int shift = 24 - 8 * level;
            int hs = shift + 8;
            for (int i = tid; i < TOTP / 4; i += 512) {
                float4 f = s4[i];
                unsigned u0 = __float_as_uint(f.x);
                unsigned u1 = __float_as_uint(f.y);
                unsigned u2 = __float_as_uint(f.z);
                unsigned u3 = __float_as_uint(f.w);
                if (u0 && (u0 >> hs) == prefix) atomicAdd(&h[(u0 >> shift) & 255], 1u);
                if (u1 && (u1 >> hs) == prefix) atomicAdd(&h[(u1 >> shift) & 255], 1u);
                if (u2 && (u2 >> hs) == prefix) atomicAdd(&h[(u2 >> shift) & 255], 1u);
                if (u3 && (u3 >> hs) == prefix) atomicAdd(&h[(u3 >> shift) & 255], 1u);
            }
            __syncthreads();
        }

        // capture current prefix/k (stable: last writes happened before a sync)
        unsigned oldpref = (level == 0) ? 0u : s_prefix;
        int k = (level == 0) ? KGLB : s_k;
        __syncthreads();

        // parallel suffix-inclusive scan of h into S
        if (tid < 256) S[tid] = h[tid];
        __syncthreads();
#pragma unroll
        for (int off = 1; off < 256; off <<= 1) {
            unsigned v = 0;
            if (tid < 256 && tid + off < 256) v = S[tid + off];
            __syncthreads();
            if (tid < 256) S[tid] += v;
            __syncthreads();
        }
        // default (fall-through keeps chosen = 0, k unchanged)
        if (tid == 0) { s_prefix = oldpref << 8; s_k = k; }
        __syncthreads();
        if (tid < 256) {
            int Si = (int)S[tid];
            int above = Si - (int)h[tid];
            if (Si >= k && above < k) {
                s_prefix = (oldpref << 8) | (unsigned)tid;
                s_k = k - above;
            }
        }
        __syncthreads();
    }

    float th = __uint_as_float(s_prefix);
    if (tid == 0) {
        g_thr[b] = th;
        g_gmax[b] = __uint_as_float(g_maxu[b]);
    }

    // ---- per-location filtered top-10 from smem (R9 logic) ----
    if (tid < NS) {
        float tv[10];
        int tc[10];
#pragma unroll
        for (int j = 0; j < 10; ++j) { tv[j] = 0.0f; tc[j] = 0; }

        const float4* r4 = (const float4*)(sA + tid * NCP);
#pragma unroll 2
        for (int i = 0; i < 38; ++i) {
            float4 f = r4[i];
            float vals[4] = {f.x, f.y, f.z, f.w};
#pragma unroll
            for (int q = 0; q < 4; ++q) {
                float a = vals[q];
                if (a >= th && a > tv[9]) {
                    float cv = a; int cc = 4 * i + q;
#pragma unroll
                    for (int j = 0; j < 10; ++j) {
                        bool sw = cv > tv[j];
                        float nv = sw ? tv[j] : cv;
                        int nc2 = sw ? tc[j] : cc;
                        tv[j] = sw ? cv : tv[j];
                        tc[j] = sw ? cc : tc[j];
                        cv = nv; cc = nc2;
                    }
                }
            }
        }
        int loc = b * NS + tid;
#pragma unroll
        for (int j = 0; j < 10; ++j) {
            g_tv[(size_t)j * NLOC + loc] = tv[j];
            g_tcb[(size_t)j * NLOC + loc] = (unsigned char)tc[j];
        }
    }
}

// ---------------------------------------------------------------------------
// Kernel 3: scatter embed + /gmax + PE + qkv from the filtered SoA top-10.
// ---------------------------------------------------------------------------
__global__ void __launch_bounds__(128) embed_qkv_kernel(
        const float* __restrict__ chan_emb,     // [150][32]
        const float* __restrict__ W,            // [96][32]
        const float* __restrict__ bias) {       // [96]
    __shared__ u64 Emb[NC * 16];
    __shared__ u64 Wp[96 * 16];
    __shared__ float bs[96];
    int tid = threadIdx.x;
    {
        const float2* e2 = (const float2*)chan_emb;
        for (int i = tid; i < NC * 16; i += 128) {
            float2 f = e2[i]; Emb[i] = pack2(f.x, f.y);
        }
        const float2* w2 = (const float2*)W;
        for (int i = tid; i < 96 * 16; i += 128) {
            float2 f = w2[i]; Wp[i] = pack2(f.x, f.y);
        }
        if (tid < 96) bs[tid] = bias[tid];
    }
    __syncthreads();

    int loc = blockIdx.x * 128 + tid;
    int b = loc / NS, s = loc - b * NS;
    float gm = g_gmax[b];
    float inv = (gm > 0.0f) ? (1.0f / gm) : 0.0f;

    u64 x[16];
#pragma unroll
    for (int t = 0; t < 16; ++t) x[t] = 0;
#pragma unroll
    for (int j = 0; j < 10; ++j) {
        float v = g_tv[(size_t)j * NLOC + loc];
        if (v > 0.0f) {
            int c = (int)g_tcb[(size_t)j * NLOC + loc];
            u64 vv = pack2(v, v);
            const u64* ep = &Emb[c * 16];
#pragma unroll
            for (int t = 0; t < 16; ++t)
                ffma2(x[t], vv, ep[t]);
        }
    }

    {
        u64 inv2 = pack2(inv, inv);
        const float4* pe4 = (const float4*)(g_pe + s * ND);
#pragma unroll
        for (int t = 0; t < 8; ++t) {
            float4 p = pe4[t];
            u64 y0 = pack2(p.x, p.y);
            u64 y1 = pack2(p.z, p.w);
            ffma2(y0, x[2 * t], inv2);
            ffma2(y1, x[2 * t + 1], inv2);
            x[2 * t] = y0;
            x[2 * t + 1] = y1;
        }
    }

    size_t qb = (size_t)b * (NHEAD * NS * HD) + (size_t)s * HD;
    const float SC = 0.3535533905932738f;  // 1/sqrt(8)

#pragma unroll 2
    for (int o = 0; o < 32; o += 4) {
        u64 a0 = 0, a1 = 0, a2 = 0, a3 = 0;
#pragma unroll
        for (int j = 0; j < 16; ++j) {
            u64 xv = x[j];
            ffma2(a0, xv, Wp[(o + 0) * 16 + j]);
            ffma2(a1, xv, Wp[(o + 1) * 16 + j]);
            ffma2(a2, xv, Wp[(o + 2) * 16 + j]);
            ffma2(a3, xv, Wp[(o + 3) * 16 + j]);
        }
        float l, h, r0, r1, r2, r3;
        unpack2(a0, l, h); r0 = (l + h + bs[o + 0]) * SC;
        unpack2(a1, l, h); r1 = (l + h + bs[o + 1]) * SC;
        unpack2(a2, l, h); r2 = (l + h + bs[o + 2]) * SC;
        unpack2(a3, l, h); r3 = (l + h + bs[o + 3]) * SC;
        *(float4*)(g_q + qb + (o >> 3) * (NS * HD) + (o & 7)) = make_float4(r0, r1, r2, r3);
    }
#pragma unroll 2
    for (int o = 32; o < 64; o += 4) {
        u64 a0 = 0, a1 = 0, a2 = 0, a3 = 0;
#pragma unroll
        for (int j = 0; j < 16; ++j) {
            u64 xv = x[j];
            ffma2(a0, xv, Wp[(o + 0) * 16 + j]);
            ffma2(a1, xv, Wp[(o + 1) * 16 + j]);
            ffma2(a2, xv, Wp[(o + 2) * 16 + j]);
            ffma2(a3, xv, Wp[(o + 3) * 16 + j]);
        }
        float l, h, r0, r1, r2, r3;
        unpack2(a0, l, h); r0 = l + h + bs[o + 0];
        unpack2(a1, l, h); r1 = l + h + bs[o + 1];
        unpack2(a2, l, h); r2 = l + h + bs[o + 2];
        unpack2(a3, l, h); r3 = l + h + bs[o + 3];
        int d = o - 32;
        *(float4*)(g_k + qb + (d >> 3) * (NS * HD) + (d & 7)) = make_float4(r0, r1, r2, r3);
    }
#pragma unroll 2
    for (int o = 64; o < 96; o += 4) {
        u64 a0 = 0, a1 = 0, a2 = 0, a3 = 0;
#pragma unroll
        for (int j = 0; j < 16; ++j) {
            u64 xv = x[j];
            ffma2(a0, xv, Wp[(o + 0) * 16 + j]);
            ffma2(a1, xv, Wp[(o + 1) * 16 + j]);
            ffma2(a2, xv, Wp[(o + 2) * 16 + j]);
            ffma2(a3, xv, Wp[(o + 3) * 16 + j]);
        }
        float l, h, r0, r1, r2, r3;
        unpack2(a0, l, h); r0 = l + h + bs[o + 0];
        unpack2(a1, l, h); r1 = l + h + bs[o + 1];
        unpack2(a2, l, h); r2 = l + h + bs[o + 2];
        unpack2(a3, l, h); r3 = l + h + bs[o + 3];
        int d = o - 64;
        *(float4*)(g_v + qb + (d >> 3) * (NS * HD) + (d & 7)) = make_float4(r0, r1, r2, r3);
    }
}

// ---------------------------------------------------------------------------
// Kernel 4: attention (R9-proven shape). Block = (b, head-pair), 224 threads,
// 2 queries/thread. Single-pass EXACT softmax via Cauchy-Schwarz bound.
// ---------------------------------------------------------------------------
__global__ void __launch_bounds__(224) attn_kernel() {
    __shared__ __align__(16) u64 K2[2 * NS * 4];
    __shared__ __align__(16) u64 V2[2 * NS * 4];
    __shared__ unsigned s_kmax[2];
    int b = blockIdx.x >> 1;
    int hp = blockIdx.x & 1;
    int tid = threadIdx.x;
    if (tid < 2) s_kmax[tid] = 0u;

    const float4* kp4 = (const float4*)(g_k + (((size_t)b * NHEAD + hp * 2) * NS) * HD);
    const float4* vp4 = (const float4*)(g_v + (((size_t)b * NHEAD + hp * 2) * NS) * HD);
    for (int i = tid; i < 2 * NS * 2; i += 224) {
        float4 f = kp4[i];
        K2[i * 2] = pack2(f.x, f.y);
        K2[i * 2 + 1] = pack2(f.z, f.w);
        float4 g = vp4[i];
        V2[i * 2] = pack2(g.x, g.y);
        V2[i * 2 + 1] = pack2(g.z, g.w);
    }
    __syncthreads();

    for (int r = tid; r < 2 * NS; r += 224) {
        u64 n2 = fmul2(K2[r * 4], K2[r * 4]);
        ffma2(n2, K2[r * 4 + 1], K2[r * 4 + 1]);
        ffma2(n2, K2[r * 4 + 2], K2[r * 4 + 2]);
        ffma2(n2, K2[r * 4 + 3], K2[r * 4 + 3]);
        float lo, hi; unpack2(n2, lo, hi);
        atomicMax(&s_kmax[r >= NS ? 1 : 0], __float_as_uint(lo + hi));
    }
    __syncthreads();

    int ha = tid / 112;
    int i = tid - ha * 112;
    if (i < 98) {
        int head = hp * 2 + ha;
        int q0 = 2 * i, q1 = 2 * i + 1;
        size_t qrow = (((size_t)b * NHEAD + head) * NS);
        const float4* qp0 = (const float4*)(g_q + (qrow + q0) * HD);
        const float4* qp1 = (const float4*)(g_q + (qrow + q1) * HD);
        float4 qa = qp0[0], qb = qp0[1], qc = qp1[0], qd = qp1[1];
        u64 Q0[4], Q1[4];
        Q0[0] = pack2(qa.x, qa.y); Q0[1] = pack2(qa.z, qa.w);
        Q0[2] = pack2(qb.x, qb.y); Q0[3] = pack2(qb.z, qb.w);
        Q1[0] = pack2(qc.x, qc.y); Q1[1] = pack2(qc.z, qc.w);
        Q1[2] = pack2(qd.x, qd.y); Q1[3] = pack2(qd.z, qd.w);

        float km = __uint_as_float(s_kmax[ha]);
        u64 n0 = fmul2(Q0[0], Q0[0]);
        ffma2(n0, Q0[1], Q0[1]); ffma2(n0, Q0[2], Q0[2]); ffma2(n0, Q0[3], Q0[3]);
        u64 n1 = fmul2(Q1[0], Q1[0]);
        ffma2(n1, Q1[1], Q1[1]); ffma2(n1, Q1[2], Q1[2]); ffma2(n1, Q1[3], Q1[3]);
        float a0, a1, b0f, b1f;
        unpack2(n0, a0, a1); unpack2(n1, b0f, b1f);
        float m0 = sqrtf((a0 + a1) * km);
        float m1 = sqrtf((b0f + b1f) * km);

        float l0 = 0.0f, l1 = 0.0f;
        u64 A0 = 0, A1 = 0, A2 = 0, A3 = 0;
        u64 B0 = 0, B1 = 0, B2 = 0, B3 = 0;
        const ulonglong2* KK = (const ulonglong2*)(K2 + ha * NS * 4);
        const ulonglong2* VV = (const ulonglong2*)(V2 + ha * NS * 4);
#pragma unroll 2
        for (int t = 0; t < NS; ++t) {
            ulonglong2 ka = KK[t * 2], kb = KK[t * 2 + 1];
            u64 d0 = fmul2(Q0[0], ka.x);
            ffma2(d0, Q0[1], ka.y); ffma2(d0, Q0[2], kb.x); ffma2(d0, Q0[3], kb.y);
            u64 d1 = fmul2(Q1[0], ka.x);
            ffma2(d1, Q1[1], ka.y); ffma2(d1, Q1[2], kb.x); ffma2(d1, Q1[3], kb.y);
            float e0, f0, e1, f1;
            unpack2(d0, e0, f0); unpack2(d1, e1, f1);
            float p0 = __expf(e0 + f0 - m0);
            float p1 = __expf(e1 + f1 - m1);
            l0 += p0; l1 += p1;
            u64 p02 = pack2(p0, p0), p12 = pack2(p1, p1);
            ulonglong2 va = VV[t * 2], vb = VV[t * 2 + 1];
            ffma2(A0, p02, va.x); ffma2(A1, p02, va.y);
            ffma2(A2, p02, vb.x); ffma2(A3, p02, vb.y);
            ffma2(B0, p12, va.x); ffma2(B1, p12, va.y);
            ffma2(B2, p12, vb.x); ffma2(B3, p12, vb.y);
        }
        float inv0 = 1.0f / l0, inv1 = 1.0f / l1;
        float o0, o1, o2, o3, o4, o5, o6, o7;
        unpack2(A0, o0, o1); unpack2(A1, o2, o3);
        unpack2(A2, o4, o5); unpack2(A3, o6, o7);
        float4* cp0 = (float4*)(g_ctx + ((size_t)b * NS + q0) * ND + head * HD);
        cp0[0] = make_float4(o0 * inv0, o1 * inv0, o2 * inv0, o3 * inv0);
        cp0[1] = make_float4(o4 * inv0, o5 * inv0, o6 * inv0, o7 * inv0);
        unpack2(B0, o0, o1); unpack2(B1, o2, o3);
        unpack2(B2, o4, o5); unpack2(B3, o6, o7);
        float4* cp1 = (float4*)(g_ctx + ((size_t)b * NS + q1) * ND + head * HD);
        cp1[0] = make_float4(o0 * inv1, o1 * inv1, o2 * inv1, o3 * inv1);
        cp1[1] = make_float4(o4 * inv1, o5 * inv1, o6 * inv1, o7 * inv1);
    }
}

// ---------------------------------------------------------------------------
// Kernel 5: out projection, f32x2 register-tiled, o-pairs. 128 thr, 2 rows.
// ---------------------------------------------------------------------------
__global__ void __launch_bounds__(128) outproj_kernel(const float* __restrict__ W,
                                                      const float* __restrict__ bias,
                                                      float* __restrict__ out) {
    __shared__ u64 Wp[32 * 16];
    __shared__ float bs[32];
    int tid = threadIdx.x;
    {
        const float2* w2 = (const float2*)W;
        for (int i = tid; i < 32 * 16; i += 128) {
            float2 f = w2[i];
            Wp[i] = pack2(f.x, f.y);
        }
        if (tid < 32) bs[tid] = bias[tid];
    }
    __syncthreads();

    int r0 = blockIdx.x * 256 + tid;
    int r1 = r0 + 128;

    u64 x0[16], x1[16];
    {
        const float4* p0 = (const float4*)(g_ctx + (size_t)r0 * ND);
        const float4* p1 = (const float4*)(g_ctx + (size_t)r1 * ND);
#pragma unroll
        for (int i = 0; i < 8; ++i) {
            float4 f = p0[i];
            x0[2 * i] = pack2(f.x, f.y); x0[2 * i + 1] = pack2(f.z, f.w);
            float4 g = p1[i];
            x1[2 * i] = pack2(g.x, g.y); x1[2 * i + 1] = pack2(g.z, g.w);
        }
    }

    float* o0p = out + (size_t)r0 * ND;
    float* o1p = out + (size_t)r1 * ND;
#pragma unroll 2
    for (int o = 0; o < 32; o += 2) {
        u64 a00 = 0, a10 = 0, a01 = 0, a11 = 0;
#pragma unroll
        for (int j = 0; j < 16; ++j) {
            u64 w0 = Wp[o * 16 + j], w1 = Wp[(o + 1) * 16 + j];
            ffma2(a00, x0[j], w0); ffma2(a10, x1[j], w0);
            ffma2(a01, x0[j], w1); ffma2(a11, x1[j], w1);
        }
        float l, h;
        unpack2(a00, l, h); o0p[o] = l + h + bs[o];
        unpack2(a10, l, h); o1p[o] = l + h + bs[o];
        unpack2(a01, l, h); o0p[o + 1] = l + h + bs[o + 1];
        unpack2(a11, l, h); o1p[o + 1] = l + h + bs[o + 1];
    }
}

// ---------------------------------------------------------------------------
extern "C" void kernel_launch(void* const* d_in, const int* in_sizes, int n_in,
                              void* d_out, int out_size) {
    const float* x          = (const float*)d_in[0];  // [1024,1,28,28]
    const float* conv1_w    = (const float*)d_in[1];  // [150,1,9,9]
    const float* chan_emb   = (const float*)d_in[2];  // [150,32]
    const float* in_proj_w  = (const float*)d_in[3];  // [96,32]
    const float* in_proj_b  = (const float*)d_in[4];  // [96]
    const float* out_proj_w = (const float*)d_in[5];  // [32,32]
    const float* out_proj_b = (const float*)d_in[6];  // [32]
    float* out = (float*)d_out;

    // Raise dynamic smem limit for the monolithic sample kernel.
    // (Attribute set, not a stream op; idempotent and deterministic.)
    cudaFuncSetAttribute(sample_kernel,
                         cudaFuncAttributeMaxDynamicSharedMemorySize,
                         SMEM_A_BYTES);

    prep_w_kernel<<<(NB * 256 + 255) / 256, 256>>>(conv1_w);
    pe_kernel<<<NS, ND>>>();
    conv_kernel<<<NB * NH, 160>>>(x);
    sample_kernel<<<NB, 512, SMEM_A_BYTES>>>();
    embed_qkv_kernel<<<NLOC / 128, 128>>>(chan_emb, in_proj_w, in_proj_b);
    attn_kernel<<<NB * 2, 224>>>();
    outproj_kernel<<<(NB * NS) / 256, 128>>>(out_proj_w, out_proj_b, out);
}

// round 16
// speedup vs baseline: 1.1720x; 1.1720x over previous
#include <cuda_runtime.h>
#include <math.h>

#define NB 1024
#define NC 150
#define NCP 152     // padded channel stride (float4-aligned); pad stays 0
#define NH 14
#define NS 196      // 14*14
#define ND 32
#define TOTP (NS * NCP)   // padded per-sample extent = 29792
#define KGLB 2352   // ceil(0.08 * 150*196)
#define NHEAD 4
#define HD 8

typedef unsigned long long u64;

__device__ __forceinline__ u64 pack2(float lo, float hi) {
    u64 r; asm("mov.b64 %0, {%1, %2};" : "=l"(r) : "f"(lo), "f"(hi)); return r;
}
__device__ __forceinline__ void unpack2(u64 v, float& lo, float& hi) {
    asm("mov.b64 {%0, %1}, %2;" : "=f"(lo), "=f"(hi) : "l"(v));
}
__device__ __forceinline__ void ffma2(u64& d, u64 a, u64 b) {
    asm("fma.rn.f32x2 %0, %1, %2, %0;" : "+l"(d) : "l"(a), "l"(b));
}
__device__ __forceinline__ u64 fmul2(u64 a, u64 b) {
    u64 r; asm("mul.rn.f32x2 %0, %1, %2;" : "=l"(r) : "l"(a), "l"(b)); return r;
}

__device__ float g_A[(size_t)NB * TOTP];           // [b][s][c], c-pad zeroed
__device__ unsigned g_cand[(size_t)NB * TOTP];     // radix-select candidates
__device__ unsigned g_hist[(size_t)NB * 256];      // level-0 hist (from conv)
__device__ unsigned g_maxu[NB];                    // per-sample max (uint view)
__device__ u64 g_wT2[81 * NC];                     // [k][c] = (w,w) splat
__device__ float g_pe[NS * ND];                    // 2D sinusoidal PE table
__device__ float g_thr[NB];
__device__ float g_gmax[NB];
__device__ float g_q[(size_t)NB * NHEAD * NS * HD];
__device__ float g_k[(size_t)NB * NHEAD * NS * HD];
__device__ float g_v[(size_t)NB * NHEAD * NS * HD];

// ---------------------------------------------------------------------------
// Kernel 0a: pre-splat conv weights + zero hist/max (graph-replay safe).
// ---------------------------------------------------------------------------
__global__ void prep_w_kernel(const float* __restrict__ w) {
    int i = blockIdx.x * blockDim.x + threadIdx.x;
    if (i < 81 * NC) {
        int k = i / NC, c = i - k * NC;
        float v = w[c * 81 + k];
        g_wT2[i] = pack2(v, v);
    }
    if (i < NB * 256) g_hist[i] = 0u;
    if (i < NB) g_maxu[i] = 0u;
}

// ---------------------------------------------------------------------------
// Kernel 0b: 2D sinusoidal PE table (batch-independent).
// ---------------------------------------------------------------------------
__global__ void pe_kernel() {
    int s = blockIdx.x;
    int d = threadIdx.x;
    int y = s / NH, xx = s - y * NH;
    const float c0 = -(logf(10000.0f) / 16.0f);
    float pe;
    if (d < 16) {
        int j = d >> 1;
        float div = expf(c0 * (float)(2 * j));
        float ang = (float)y * div;
        pe = (d & 1) ? cosf(ang) : sinf(ang);
    } else {
        int dd = d - 16;
        int j = dd >> 1;
        float div = expf(c0 * (float)(2 * j));
        float ang = (float)xx * div;
        pe = (dd & 1) ? cosf(ang) : sinf(ang);
    }
    g_pe[s * ND + d] = pe;
}

// ---------------------------------------------------------------------------
// Kernel 1: conv 9x9 stride2 pad4 + ReLU, f32x2 over ow-pairs.
// FUSED: level-0 radix hist + per-sample max (R9-proven, verbatim).
// ---------------------------------------------------------------------------
__global__ void __launch_bounds__(160) conv_kernel(const float* __restrict__ x) {
    __shared__ float row[9][36];
    __shared__ u64 row2[9][33];
    __shared__ unsigned s_hist[256];
    __shared__ unsigned s_maxu;
    int b = blockIdx.x / NH;
    int oh = blockIdx.x % NH;
    int tid = threadIdx.x;

    for (int i = tid; i < 9 * 36; i += 160)
        (&row[0][0])[i] = 0.0f;
    for (int i = tid; i < 256; i += 160) s_hist[i] = 0u;
    if (tid == 0) s_maxu = 0u;
    __syncthreads();
    for (int i = tid; i < 9 * 28; i += 160) {
        int kh = i / 28, iw = i % 28;
        int ih = oh * 2 - 4 + kh;
        if (ih >= 0 && ih < 28)
            row[kh][iw + 4] = x[((size_t)b * 28 + ih) * 28 + iw];
    }
    __syncthreads();
    for (int i = tid; i < 9 * 33; i += 160) {
        int kh = i / 33, j = i - kh * 33;
        row2[kh][j] = pack2(row[kh][j], row[kh][j + 2]);
    }
    __syncthreads();

    int c = tid;
    if (c < NC) {
        u64 acc[7];
#pragma unroll
        for (int p = 0; p < 7; ++p) acc[p] = 0;
        for (int kh = 0; kh < 9; ++kh) {
            u64 rr2[33];
#pragma unroll
            for (int j = 0; j < 33; ++j) rr2[j] = row2[kh][j];
            const u64* wp = &g_wT2[(kh * 9) * NC + c];
#pragma unroll
            for (int kw = 0; kw < 9; ++kw) {
                u64 w2 = wp[kw * NC];
#pragma unroll
                for (int p = 0; p < 7; ++p)
                    ffma2(acc[p], w2, rr2[4 * p + kw]);
            }
        }
        float* out = &g_A[((size_t)b * NS + oh * NH) * NCP + c];
        unsigned mymax = 0u;
#pragma unroll
        for (int p = 0; p < 7; ++p) {
            float lo, hi; unpack2(acc[p], lo, hi);
            lo = fmaxf(lo, 0.0f);
            hi = fmaxf(hi, 0.0f);
            out[(size_t)(2 * p) * NCP] = lo;
            out[(size_t)(2 * p + 1) * NCP] = hi;
            unsigned ul = __float_as_uint(lo);
            unsigned uh = __float_as_uint(hi);
            mymax = max(mymax, max(ul, uh));
            if (ul) atomicAdd(&s_hist[ul >> 24], 1u);
            if (uh) atomicAdd(&s_hist[uh >> 24], 1u);
        }
        atomicMax(&s_maxu, mymax);
    }
    __syncthreads();
    for (int i = tid; i < 256; i += 160) {
        unsigned cc = s_hist[i];
        if (cc) atomicAdd(&g_hist[(size_t)b * 256 + i], cc);
    }
    if (tid == 0) atomicMax(&g_maxu[b], s_maxu);
}

// ---------------------------------------------------------------------------
// Kernel 2: per-sample exact KGLB-th largest (R9-proven, verbatim).
// Level 0 from conv hist; level 1 full pass (8 vals/iter) compacts
// candidates; levels 2-3 scan the compact list.
// ---------------------------------------------------------------------------
__global__ void select_kernel() {
    int b = blockIdx.x;
    const float4* base4 = (const float4*)(g_A + (size_t)b * TOTP);
    unsigned* cand = g_cand + (size_t)b * TOTP;
    __shared__ unsigned hist[256];
    __shared__ unsigned s_prefix;
    __shared__ int s_k;
    __shared__ int s_cnt;
    int tid = threadIdx.x;
    int nt = blockDim.x;
    if (tid == 0) s_cnt = 0;

    for (int i = tid; i < 256; i += nt) hist[i] = g_hist[(size_t)b * 256 + i];
    __syncthreads();
    if (tid == 0) {
        int cum = 0; unsigned chosen = 0; int kk = KGLB;
        for (int bin = 255; bin >= 0; --bin) {
            int c = (int)hist[bin];
            if (cum + c >= KGLB) { chosen = (unsigned)bin; kk = KGLB - cum; break; }
            cum += c;
        }
        s_prefix = chosen; s_k = kk;
    }
    __syncthreads();
    unsigned prefix = s_prefix;
    int k = s_k;

    for (int i = tid; i < 256; i += nt) hist[i] = 0;
    __syncthreads();
    for (int i = tid; i < TOTP / 8; i += nt) {
        float4 f0 = base4[2 * i];
        float4 f1 = base4[2 * i + 1];
        unsigned u0 = __float_as_uint(f0.x);
        unsigned u1 = __float_as_uint(f0.y);
        unsigned u2 = __float_as_uint(f0.z);
        unsigned u3 = __float_as_uint(f0.w);
        unsigned u4 = __float_as_uint(f1.x);
        unsigned u5 = __float_as_uint(f1.y);
        unsigned u6 = __float_as_uint(f1.z);
        unsigned u7 = __float_as_uint(f1.w);
        if (u0 && (u0 >> 24) == prefix) { cand[atomicAdd(&s_cnt, 1)] = u0; atomicAdd(&hist[(u0 >> 16) & 255], 1u); }
        if (u1 && (u1 >> 24) == prefix) { cand[atomicAdd(&s_cnt, 1)] = u1; atomicAdd(&hist[(u1 >> 16) & 255], 1u); }
        if (u2 && (u2 >> 24) == prefix) { cand[atomicAdd(&s_cnt, 1)] = u2; atomicAdd(&hist[(u2 >> 16) & 255], 1u); }
        if (u3 && (u3 >> 24) == prefix) { cand[atomicAdd(&s_cnt, 1)] = u3; atomicAdd(&hist[(u3 >> 16) & 255], 1u); }
        if (u4 && (u4 >> 24) == prefix) { cand[atomicAdd(&s_cnt, 1)] = u4; atomicAdd(&hist[(u4 >> 16) & 255], 1u); }
        if (u5 && (u5 >> 24) == prefix) { cand[atomicAdd(&s_cnt, 1)] = u5; atomicAdd(&hist[(u5 >> 16) & 255], 1u); }
        if (u6 && (u6 >> 24) == prefix) { cand[atomicAdd(&s_cnt, 1)] = u6; atomicAdd(&hist[(u6 >> 16) & 255], 1u); }
        if (u7 && (u7 >> 24) == prefix) { cand[atomicAdd(&s_cnt, 1)] = u7; atomicAdd(&hist[(u7 >> 16) & 255], 1u); }
    }
    __syncthreads();
    int cnt = s_cnt;
    if (tid == 0) {
        int cum = 0; unsigned chosen = 0; int kk = k;
        for (int bin = 255; bin >= 0; --bin) {
            int c = (int)hist[bin];
            if (cum + c >= k) { chosen = (unsigned)bin; kk = k - cum; break; }
            cum += c;
        }
        s_prefix = (prefix << 8) | chosen; s_k = kk;
    }
    __syncthreads();
    prefix = s_prefix; k = s_k;

    for (int i = tid; i < 256; i += nt) hist[i] = 0;
    __syncthreads();
    for (int i = tid; i < cnt; i += nt) {
        unsigned u = cand[i];
        if ((u >> 16) == prefix) atomicAdd(&hist[(u >> 8) & 255], 1u);
    }
    __syncthreads();
    if (tid == 0) {
        int cum = 0; unsigned chosen = 0; int kk = k;
        for (int bin = 255; bin >= 0; --bin) {
            int c = (int)hist[bin];
            if (cum + c >= k) { chosen = (unsigned)bin; kk = k - cum; break; }
            cum += c;
        }
        s_prefix = (prefix << 8) | chosen; s_k = kk;
    }
    __syncthreads();
    prefix = s_prefix; k = s_k;

    for (int i = tid; i < 256; i += nt) hist[i] = 0;
    __syncthreads();
    for (int i = tid; i < cnt; i += nt) {
        unsigned u = cand[i];
        if ((u >> 8) == prefix) atomicAdd(&hist[u & 255], 1u);
    }
    __syncthreads();
    if (tid == 0) {
        int cum = 0; unsigned chosen = 0;
        for (int bin = 255; bin >= 0; --bin) {
            int c = (int)hist[bin];
            if (cum + c >= k) { chosen = (unsigned)bin; break; }
            cum += c;
        }
        g_thr[b] = __uint_as_float((prefix << 8) | chosen);
        g_gmax[b] = __uint_as_float(g_maxu[b]);
    }
}

// ---------------------------------------------------------------------------
// Kernel 3 (FUSED): per-location top-10 + scatter embed + /gmax + PE + qkv.
// (R9-proven, verbatim.)
// ---------------------------------------------------------------------------
__global__ void __launch_bounds__(128) topk_qkv_kernel(
        const float* __restrict__ chan_emb,     // [150][32]
        const float* __restrict__ W,            // [96][32]
        const float* __restrict__ bias) {       // [96]
    __shared__ u64 Emb[NC * 16];
    __shared__ u64 Wp[96 * 16];
    __shared__ float bs[96];
    int tid = threadIdx.x;
    {
        const float2* e2 = (const float2*)chan_emb;
        for (int i = tid; i < NC * 16; i += 128) {
            float2 f = e2[i]; Emb[i] = pack2(f.x, f.y);
        }
        const float2* w2 = (const float2*)W;
        for (int i = tid; i < 96 * 16; i += 128) {
            float2 f = w2[i]; Wp[i] = pack2(f.x, f.y);
        }
        if (tid < 96) bs[tid] = bias[tid];
    }
    __syncthreads();

    int loc = blockIdx.x * 128 + tid;
    int b = loc / NS, s = loc - b * NS;
    float th = g_thr[b];
    float gm = g_gmax[b];
    float inv = (gm > 0.0f) ? (1.0f / gm) : 0.0f;

    float tv[10];
    int tc[10];
#pragma unroll
    for (int j = 0; j < 10; ++j) { tv[j] = 0.0f; tc[j] = 0; }

    const float4* r4 = (const float4*)(g_A + (size_t)loc * NCP);
#pragma unroll 4
    for (int i = 0; i < 38; ++i) {
        float4 f = r4[i];
        float vals[4] = {f.x, f.y, f.z, f.w};
#pragma unroll
        for (int q = 0; q < 4; ++q) {
            float a = vals[q];
            if (a >= th && a > tv[9]) {
                float cv = a; int cc = 4 * i + q;
#pragma unroll
                for (int j = 0; j < 10; ++j) {
                    bool sw = cv > tv[j];
                    float nv = sw ? tv[j] : cv;
                    int nc2 = sw ? tc[j] : cc;
                    tv[j] = sw ? cv : tv[j];
                    tc[j] = sw ? cc : tc[j];
                    cv = nv; cc = nc2;
                }
            }
        }
    }

    u64 x[16];
#pragma unroll
    for (int t = 0; t < 16; ++t) x[t] = 0;
#pragma unroll
    for (int j = 0; j < 10; ++j) {
        if (tv[j] > 0.0f) {
            u64 vv = pack2(tv[j], tv[j]);
            const u64* ep = &Emb[tc[j] * 16];
#pragma unroll
            for (int t = 0; t < 16; ++t)
                ffma2(x[t], vv, ep[t]);
        }
    }

    {
        u64 inv2 = pack2(inv, inv);
        const float4* pe4 = (const float4*)(g_pe + s * ND);
#pragma unroll
        for (int t = 0; t < 8; ++t) {
            float4 p = pe4[t];
            u64 y0 = pack2(p.x, p.y);
            u64 y1 = pack2(p.z, p.w);
            ffma2(y0, x[2 * t], inv2);
            ffma2(y1, x[2 * t + 1], inv2);
            x[2 * t] = y0;
            x[2 * t + 1] = y1;
        }
    }

    size_t qb = (size_t)b * (NHEAD * NS * HD) + (size_t)s * HD;
    const float SC = 0.3535533905932738f;  // 1/sqrt(8)

#pragma unroll 2
    for (int o = 0; o < 32; o += 4) {
        u64 a0 = 0, a1 = 0, a2 = 0, a3 = 0;
#pragma unroll
        for (int j = 0; j < 16; ++j) {
            u64 xv = x[j];
            ffma2(a0, xv, Wp[(o + 0) * 16 + j]);
            ffma2(a1, xv, Wp[(o + 1) * 16 + j]);
            ffma2(a2, xv, Wp[(o + 2) * 16 + j]);
            ffma2(a3, xv, Wp[(o + 3) * 16 + j]);
        }
        float l, h, r0, r1, r2, r3;
        unpack2(a0, l, h); r0 = (l + h + bs[o + 0]) * SC;
        unpack2(a1, l, h); r1 = (l + h + bs[o + 1]) * SC;
        unpack2(a2, l, h); r2 = (l + h + bs[o + 2]) * SC;
        unpack2(a3, l, h); r3 = (l + h + bs[o + 3]) * SC;
        *(float4*)(g_q + qb + (o >> 3) * (NS * HD) + (o & 7)) = make_float4(r0, r1, r2, r3);
    }
#pragma unroll 2
    for (int o = 32; o < 64; o += 4) {
        u64 a0 = 0, a1 = 0, a2 = 0, a3 = 0;
#pragma unroll
        for (int j = 0; j < 16; ++j) {
            u64 xv = x[j];
            ffma2(a0, xv, Wp[(o + 0) * 16 + j]);
            ffma2(a1, xv, Wp[(o + 1) * 16 + j]);
            ffma2(a2, xv, Wp[(o + 2) * 16 + j]);
            ffma2(a3, xv, Wp[(o + 3) * 16 + j]);
        }
        float l, h, r0, r1, r2, r3;
        unpack2(a0, l, h); r0 = l + h + bs[o + 0];
        unpack2(a1, l, h); r1 = l + h + bs[o + 1];
        unpack2(a2, l, h); r2 = l + h + bs[o + 2];
        unpack2(a3, l, h); r3 = l + h + bs[o + 3];
        int d = o - 32;
        *(float4*)(g_k + qb + (d >> 3) * (NS * HD) + (d & 7)) = make_float4(r0, r1, r2, r3);
    }
#pragma unroll 2
    for (int o = 64; o < 96; o += 4) {
        u64 a0 = 0, a1 = 0, a2 = 0, a3 = 0;
#pragma unroll
        for (int j = 0; j < 16; ++j) {
            u64 xv = x[j];
            ffma2(a0, xv, Wp[(o + 0) * 16 + j]);
            ffma2(a1, xv, Wp[(o + 1) * 16 + j]);
            ffma2(a2, xv, Wp[(o + 2) * 16 + j]);
            ffma2(a3, xv, Wp[(o + 3) * 16 + j]);
        }
        float l, h, r0, r1, r2, r3;
        unpack2(a0, l, h); r0 = l + h + bs[o + 0];
        unpack2(a1, l, h); r1 = l + h + bs[o + 1];
        unpack2(a2, l, h); r2 = l + h + bs[o + 2];
        unpack2(a3, l, h); r3 = l + h + bs[o + 3];
        int d = o - 64;
        *(float4*)(g_v + qb + (d >> 3) * (NS * HD) + (d & 7)) = make_float4(r0, r1, r2, r3);
    }
}

// ---------------------------------------------------------------------------
// Kernel 4 (FUSED attn+outproj): one block per SAMPLE, 392 threads.
// Attention phase: thread = (head = tid/98, i = tid%98), queries 2i, 2i+1 --
// exactly the R9-proven per-thread shape, all lanes active, all 4 heads'
// K/V in smem. Single-pass EXACT softmax (Cauchy-Schwarz bound).
// Then ctx -> smem (reusing K2, exact 25088B fit) and in-block 32x32
// out-projection (2 threads/row x 16 outputs) straight to `out`.
// No warp collectives anywhere (partial warp at 392 threads is safe).
// ---------------------------------------------------------------------------
__global__ void __launch_bounds__(392) attn_out_kernel(
        const float* __restrict__ W,     // [32][32]
        const float* __restrict__ bias,  // [32]
        float* __restrict__ out) {
    __shared__ __align__(16) u64 K2[NHEAD * NS * 4];   // 25088 B
    __shared__ __align__(16) u64 V2[NHEAD * NS * 4];   // 25088 B
    __shared__ u64 Wp[32 * 16];                        // 4096 B
    __shared__ float bs[32];
    __shared__ unsigned s_kmax[NHEAD];
    int b = blockIdx.x;
    int tid = threadIdx.x;

    {
        const float2* w2 = (const float2*)W;
        for (int i = tid; i < 32 * 16; i += 392) {
            float2 f = w2[i]; Wp[i] = pack2(f.x, f.y);
        }
        if (tid < 32) bs[tid] = bias[tid];
        if (tid < NHEAD) s_kmax[tid] = 0u;
    }

    const float4* kp4 = (const float4*)(g_k + ((size_t)b * NHEAD * NS) * HD);
    const float4* vp4 = (const float4*)(g_v + ((size_t)b * NHEAD * NS) * HD);
    for (int i = tid; i < NHEAD * NS * 2; i += 392) {
        float4 f = kp4[i];
        K2[i * 2] = pack2(f.x, f.y);
        K2[i * 2 + 1] = pack2(f.z, f.w);
        float4 g = vp4[i];
        V2[i * 2] = pack2(g.x, g.y);
        V2[i * 2 + 1] = pack2(g.z, g.w);
    }
    __syncthreads();

    // per-row |k|^2 -> per-head max (smem atomics; no warp collectives)
    for (int r = tid; r < NHEAD * NS; r += 392) {
        u64 n2 = fmul2(K2[r * 4], K2[r * 4]);
        ffma2(n2, K2[r * 4 + 1], K2[r * 4 + 1]);
        ffma2(n2, K2[r * 4 + 2], K2[r * 4 + 2]);
        ffma2(n2, K2[r * 4 + 3], K2[r * 4 + 3]);
        float lo, hi; unpack2(n2, lo, hi);
        atomicMax(&s_kmax[r / NS], __float_as_uint(lo + hi));
    }
    __syncthreads();

    int head = tid / 98;
    int i = tid - head * 98;
    int q0 = 2 * i, q1 = 2 * i + 1;
    size_t qrow = (((size_t)b * NHEAD + head) * NS);
    const float4* qp0 = (const float4*)(g_q + (qrow + q0) * HD);
    const float4* qp1 = (const float4*)(g_q + (qrow + q1) * HD);
    float4 qa = qp0[0], qb = qp0[1], qc = qp1[0], qd = qp1[1];
    u64 Q0[4], Q1[4];
    Q0[0] = pack2(qa.x, qa.y); Q0[1] = pack2(qa.z, qa.w);
    Q0[2] = pack2(qb.x, qb.y); Q0[3] = pack2(qb.z, qb.w);
    Q1[0] = pack2(qc.x, qc.y); Q1[1] = pack2(qc.z, qc.w);
    Q1[2] = pack2(qd.x, qd.y); Q1[3] = pack2(qd.z, qd.w);

    float km = __uint_as_float(s_kmax[head]);
    u64 n0 = fmul2(Q0[0], Q0[0]);
    ffma2(n0, Q0[1], Q0[1]); ffma2(n0, Q0[2], Q0[2]); ffma2(n0, Q0[3], Q0[3]);
    u64 n1 = fmul2(Q1[0], Q1[0]);
    ffma2(n1, Q1[1], Q1[1]); ffma2(n1, Q1[2], Q1[2]); ffma2(n1, Q1[3], Q1[3]);
    float a0, a1, b0f, b1f;
    unpack2(n0, a0, a1); unpack2(n1, b0f, b1f);
    float m0 = sqrtf((a0 + a1) * km);
    float m1 = sqrtf((b0f + b1f) * km);

    float l0 = 0.0f, l1 = 0.0f;
    u64 A0 = 0, A1 = 0, A2 = 0, A3 = 0;
    u64 B0 = 0, B1 = 0, B2 = 0, B3 = 0;
    const ulonglong2* KK = (const ulonglong2*)(K2 + head * NS * 4);
    const ulonglong2* VV = (const ulonglong2*)(V2 + head * NS * 4);
#pragma unroll 2
    for (int t = 0; t < NS; ++t) {
        ulonglong2 ka = KK[t * 2], kb = KK[t * 2 + 1];
        u64 d0 = fmul2(Q0[0], ka.x);
        ffma2(d0, Q0[1], ka.y); ffma2(d0, Q0[2], kb.x); ffma2(d0, Q0[3], kb.y);
        u64 d1 = fmul2(Q1[0], ka.x);
        ffma2(d1, Q1[1], ka.y); ffma2(d1, Q1[2], kb.x); ffma2(d1, Q1[3], kb.y);
        float e0, f0, e1, f1;
        unpack2(d0, e0, f0); unpack2(d1, e1, f1);
        float p0 = __expf(e0 + f0 - m0);
        float p1 = __expf(e1 + f1 - m1);
        l0 += p0; l1 += p1;
        u64 p02 = pack2(p0, p0), p12 = pack2(p1, p1);
        ulonglong2 va = VV[t * 2], vb = VV[t * 2 + 1];
        ffma2(A0, p02, va.x); ffma2(A1, p02, va.y);
        ffma2(A2, p02, vb.x); ffma2(A3, p02, vb.y);
        ffma2(B0, p12, va.x); ffma2(B1, p12, va.y);
        ffma2(B2, p12, vb.x); ffma2(B3, p12, vb.y);
    }
    float inv0 = 1.0f / l0, inv1 = 1.0f / l1;

    // ---- ctx into smem, reusing K2 (all K2/V2 reads are done) ----
    __syncthreads();
    float* ctxs = (float*)K2;    // [196][32] floats = 25088 B, exact fit
    {
        float o0, o1, o2, o3, o4, o5, o6, o7;
        unpack2(A0, o0, o1); unpack2(A1, o2, o3);
        unpack2(A2, o4, o5); unpack2(A3, o6, o7);
        float4* cp0 = (float4*)(ctxs + q0 * ND + head * HD);
        cp0[0] = make_float4(o0 * inv0, o1 * inv0, o2 * inv0, o3 * inv0);
        cp0[1] = make_float4(o4 * inv0, o5 * inv0, o6 * inv0, o7 * inv0);
        unpack2(B0, o0, o1); unpack2(B1, o2, o3);
        unpack2(B2, o4, o5); unpack2(B3, o6, o7);
        float4* cp1 = (float4*)(ctxs + q1 * ND + head * HD);
        cp1[0] = make_float4(o0 * inv1, o1 * inv1, o2 * inv1, o3 * inv1);
        cp1[1] = make_float4(o4 * inv1, o5 * inv1, o6 * inv1, o7 * inv1);
    }
    __syncthreads();

    // ---- out projection in-block: 2 threads/row, 16 outputs each ----
    int r = tid % NS;
    int half = tid / NS;      // 0 or 1
    u64 x[16];
    {
        const float4* p = (const float4*)(ctxs + r * ND);
#pragma unroll
        for (int t = 0; t < 8; ++t) {
            float4 f = p[t];
            x[2 * t] = pack2(f.x, f.y);
            x[2 * t + 1] = pack2(f.z, f.w);
        }
    }
    float* op = out + ((size_t)b * NS + r) * ND;
    int obase = half * 16;
#pragma unroll
    for (int og = 0; og < 16; og += 4) {
        int o = obase + og;
        u64 a0c = 0, a1c = 0, a2c = 0, a3c = 0;
#pragma unroll
        for (int j = 0; j < 16; ++j) {
            u64 xv = x[j];
            ffma2(a0c, xv, Wp[(o + 0) * 16 + j]);
            ffma2(a1c, xv, Wp[(o + 1) * 16 + j]);
            ffma2(a2c, xv, Wp[(o + 2) * 16 + j]);
            ffma2(a3c, xv, Wp[(o + 3) * 16 + j]);
        }
        float l, h, r0, r1, r2, r3;
        unpack2(a0c, l, h); r0 = l + h + bs[o + 0];
        unpack2(a1c, l, h); r1 = l + h + bs[o + 1];
        unpack2(a2c, l, h); r2 = l + h + bs[o + 2];
        unpack2(a3c, l, h); r3 = l + h + bs[o + 3];
        *(float4*)(op + o) = make_float4(r0, r1, r2, r3);
    }
}

// ---------------------------------------------------------------------------
extern "C" void kernel_launch(void* const* d_in, const int* in_sizes, int n_in,
                              void* d_out, int out_size) {
    const float* x          = (const float*)d_in[0];  // [1024,1,28,28]
    const float* conv1_w    = (const float*)d_in[1];  // [150,1,9,9]
    const float* chan_emb   = (const float*)d_in[2];  // [150,32]
    const float* in_proj_w  = (const float*)d_in[3];  // [96,32]
    const float* in_proj_b  = (const float*)d_in[4];  // [96]
    const float* out_proj_w = (const float*)d_in[5];  // [32,32]
    const float* out_proj_b = (const float*)d_in[6];  // [32]
    float* out = (float*)d_out;

    prep_w_kernel<<<(NB * 256 + 255) / 256, 256>>>(conv1_w);
    pe_kernel<<<NS, ND>>>();
    conv_kernel<<<NB * NH, 160>>>(x);
    select_kernel<<<NB, 512>>>();
    topk_qkv_kernel<<<(NB * NS) / 128, 128>>>(chan_emb, in_proj_w, in_proj_b);
    attn_out_kernel<<<NB, 392>>>(out_proj_w, out_proj_b, out);
}